// round 1
// baseline (speedup 1.0000x reference)
#include <cuda_runtime.h>
#include <math.h>

// Problem constants
#define MDIM 4096
#define NDIM 8192
#define DDIM 64

// Tiling
#define BM 128
#define BN 128
#define NSPLIT 16
#define NCOLS (NDIM / NSPLIT)   // 512
#define NTILES (NCOLS / BN)     // 4
#define SSTRIDE 132             // smem row stride in floats (k-major), 16B-aligned rows

#define LOG2E 1.4426950408889634f

// Scratch (no allocations allowed — device globals)
__device__ float g_c[MDIM];                 // (t1 - 0.5*|xe|^2/s2) * log2(e)
__device__ float g_d[NDIM];                 // (-0.5*|xb|^2/s2) * log2(e)
__device__ float g_partial[NSPLIT * MDIM];  // per-slab row partial sums

__device__ __forceinline__ float ex2_approx(float x) {
    float r;
    asm("ex2.approx.ftz.f32 %0, %1;" : "=f"(r) : "f"(x));
    return r;
}

// ---------------------------------------------------------------------------
// Kernel P: per-row constants in log2 domain.
// ---------------------------------------------------------------------------
__global__ void kde_precompute(const float* __restrict__ xe,
                               const float* __restrict__ xb,
                               const float* __restrict__ logsig) {
    int i = blockIdx.x * blockDim.x + threadIdx.x;
    float ls = logsig[0];
    float inv_s2 = __expf(-2.0f * ls);      // 1/sigma^2
    // t1 = -0.5*D*log(2*pi) - log_sigma
    float t1 = -0.5f * (float)DDIM * 1.8378770664093453f - ls;

    if (i < MDIM) {
        const float4* p = (const float4*)(xe + (size_t)i * DDIM);
        float s = 0.0f;
#pragma unroll
        for (int k = 0; k < DDIM / 4; k++) {
            float4 v = p[k];
            s += v.x * v.x + v.y * v.y + v.z * v.z + v.w * v.w;
        }
        g_c[i] = (t1 - 0.5f * s * inv_s2) * LOG2E;
    }
    int j = i - MDIM;
    if (j >= 0 && j < NDIM) {
        const float4* p = (const float4*)(xb + (size_t)j * DDIM);
        float s = 0.0f;
#pragma unroll
        for (int k = 0; k < DDIM / 4; k++) {
            float4 v = p[k];
            s += v.x * v.x + v.y * v.y + v.z * v.z + v.w * v.w;
        }
        g_d[j] = (-0.5f * s * inv_s2) * LOG2E;
    }
}

// ---------------------------------------------------------------------------
// Main kernel: 128x128 tile per block, 256 threads, 8x8 register tile.
// Exponent e2 (log2 domain) = c_m + d_n + cross * (log2e / s2).
// Underflow-skip: only touch MUFU if some element can be representable.
// ---------------------------------------------------------------------------
__global__ __launch_bounds__(256)
void kde_main(const float* __restrict__ xe,
              const float* __restrict__ xb,
              const float* __restrict__ logsig) {
    extern __shared__ float sm[];
    float* As = sm;                    // [DDIM][SSTRIDE] k-major eval tile
    float* Bs = sm + DDIM * SSTRIDE;   // [DDIM][SSTRIDE] k-major base tile

    const int tid = threadIdx.x;
    const int ty = tid >> 4;           // 0..15 (row group)
    const int tx = tid & 15;           // 0..15 (col group)
    const int m0 = blockIdx.x * BM;
    const int c0 = blockIdx.y * NCOLS;

    const float ls = logsig[0];
    const float gscale = __expf(-2.0f * ls) * LOG2E;   // log2e / sigma^2

    // --- load + transpose x_eval tile into As (once per block) ---
    {
        const float4* xe4 = (const float4*)xe;
#pragma unroll
        for (int it = 0; it < (BM * (DDIM / 4)) / 256; it++) {
            int i = it * 256 + tid;
            int row = i >> 4;          // 0..127
            int k4 = i & 15;           // 0..15
            float4 v = xe4[(size_t)(m0 + row) * (DDIM / 4) + k4];
            int k = k4 * 4;
            As[(k + 0) * SSTRIDE + row] = v.x;
            As[(k + 1) * SSTRIDE + row] = v.y;
            As[(k + 2) * SSTRIDE + row] = v.z;
            As[(k + 3) * SSTRIDE + row] = v.w;
        }
    }

    // per-thread row constants
    float cm[8];
#pragma unroll
    for (int u = 0; u < 4; u++) {
        cm[u]     = __ldg(&g_c[m0 + ty * 4 + u]);
        cm[u + 4] = __ldg(&g_c[m0 + 64 + ty * 4 + u]);
    }

    float rowacc[8];
#pragma unroll
    for (int u = 0; u < 8; u++) rowacc[u] = 0.0f;

    const float4* xb4 = (const float4*)xb;

    for (int t = 0; t < NTILES; t++) {
        const int n0 = c0 + t * BN;
        __syncthreads();   // protect Bs from previous iteration's readers
        // --- load + transpose x_base tile into Bs ---
#pragma unroll
        for (int it = 0; it < (BN * (DDIM / 4)) / 256; it++) {
            int i = it * 256 + tid;
            int row = i >> 4;
            int k4 = i & 15;
            float4 v = xb4[(size_t)(n0 + row) * (DDIM / 4) + k4];
            int k = k4 * 4;
            Bs[(k + 0) * SSTRIDE + row] = v.x;
            Bs[(k + 1) * SSTRIDE + row] = v.y;
            Bs[(k + 2) * SSTRIDE + row] = v.z;
            Bs[(k + 3) * SSTRIDE + row] = v.w;
        }
        __syncthreads();

        float dn[8];
#pragma unroll
        for (int u = 0; u < 4; u++) {
            dn[u]     = __ldg(&g_d[n0 + tx * 4 + u]);
            dn[u + 4] = __ldg(&g_d[n0 + 64 + tx * 4 + u]);
        }

        float cross[8][8];
#pragma unroll
        for (int i = 0; i < 8; i++)
#pragma unroll
            for (int j = 0; j < 8; j++) cross[i][j] = 0.0f;

        // --- mainloop over D: outer product accumulation ---
#pragma unroll 8
        for (int k = 0; k < DDIM; k++) {
            float4 a0 = *(const float4*)&As[k * SSTRIDE + ty * 4];
            float4 a1 = *(const float4*)&As[k * SSTRIDE + 64 + ty * 4];
            float4 b0 = *(const float4*)&Bs[k * SSTRIDE + tx * 4];
            float4 b1 = *(const float4*)&Bs[k * SSTRIDE + 64 + tx * 4];
            float a[8] = {a0.x, a0.y, a0.z, a0.w, a1.x, a1.y, a1.z, a1.w};
            float b[8] = {b0.x, b0.y, b0.z, b0.w, b1.x, b1.y, b1.z, b1.w};
#pragma unroll
            for (int i = 0; i < 8; i++)
#pragma unroll
                for (int j = 0; j < 8; j++)
                    cross[i][j] = fmaf(a[i], b[j], cross[i][j]);
        }

        // --- epilogue: exponent in log2 domain + underflow skip ---
        float mxi[8];
#pragma unroll
        for (int i = 0; i < 8; i++) {
            float mi = -1e30f;
#pragma unroll
            for (int j = 0; j < 8; j++) {
                float e = fmaf(cross[i][j], gscale, cm[i] + dn[j]);
                cross[i][j] = e;
                mi = fmaxf(mi, e);
            }
            mxi[i] = mi;
        }
        float mx = fmaxf(fmaxf(fmaxf(mxi[0], mxi[1]), fmaxf(mxi[2], mxi[3])),
                         fmaxf(fmaxf(mxi[4], mxi[5]), fmaxf(mxi[6], mxi[7])));
        if (mx > -125.0f) {   // anything below 2^-125 is numerically invisible
#pragma unroll
            for (int i = 0; i < 8; i++) {
                float s = 0.0f;
#pragma unroll
                for (int j = 0; j < 8; j++) s += ex2_approx(cross[i][j]);
                rowacc[i] += s;
            }
        }
    }

    // --- reduce rowacc across the 16 tx threads (16-lane shuffle halves) ---
#pragma unroll
    for (int u = 0; u < 8; u++) {
        float v = rowacc[u];
#pragma unroll
        for (int o = 1; o < 16; o <<= 1)
            v += __shfl_xor_sync(0xffffffffu, v, o);
        if (tx == 0) {
            int mrow = (u < 4) ? (m0 + ty * 4 + u) : (m0 + 64 + ty * 4 + (u - 4));
            g_partial[blockIdx.y * MDIM + mrow] = v;
        }
    }
}

// ---------------------------------------------------------------------------
// Finalize: out[m] = log(EPS + (sum over slabs)/N)
// ---------------------------------------------------------------------------
__global__ void kde_finalize(float* __restrict__ out) {
    int m = blockIdx.x * blockDim.x + threadIdx.x;
    if (m >= MDIM) return;
    float s = 0.0f;
#pragma unroll
    for (int g = 0; g < NSPLIT; g++) s += g_partial[g * MDIM + m];
    out[m] = logf(1e-8f + s * (1.0f / (float)NDIM));
}

// ---------------------------------------------------------------------------
extern "C" void kernel_launch(void* const* d_in, const int* in_sizes, int n_in,
                              void* d_out, int out_size) {
    const float* xe = (const float*)d_in[0];   // x_eval [4096,64]
    const float* xb = (const float*)d_in[1];   // x_base [8192,64]
    const float* ls = (const float*)d_in[2];   // log_sigma [1]
    float* out = (float*)d_out;                // [4096]

    size_t smem = (size_t)2 * DDIM * SSTRIDE * sizeof(float);  // 67584 B
    cudaFuncSetAttribute(kde_main, cudaFuncAttributeMaxDynamicSharedMemorySize,
                         (int)smem);

    kde_precompute<<<(MDIM + NDIM + 255) / 256, 256>>>(xe, xb, ls);
    dim3 grid(MDIM / BM, NSPLIT);
    kde_main<<<grid, 256, smem>>>(xe, xb, ls);
    kde_finalize<<<(MDIM + 255) / 256, 256>>>(out);
}

// round 2
// speedup vs baseline: 29.3667x; 29.3667x over previous
#include <cuda_runtime.h>
#include <math.h>

// Problem constants
#define MDIM 4096
#define NDIM 8192
#define DDIM 64

// Tiling (fallback GEMM path)
#define BM 128
#define BN 128
#define NSPLIT 16
#define NCOLS (NDIM / NSPLIT)   // 512
#define NTILES (NCOLS / BN)     // 4
#define SSTRIDE 132             // smem row stride in floats (k-major)

#define LOG2E 1.4426950408889634f
#define EPSV  1e-8f

// Global-skip bound: t2 = -0.5*sq/sigma^2 <= 0 always, so
//   val = (1/n) * sum exp(t1 + t2) <= exp(t1).
// If t1 <= T1_SKIP (= -46), then val <= 1e-20, and
//   |log(EPS + val) - log(EPS)| <= val/EPS <= 1e-12  (below fp32 ulp).
// This bound holds for ARBITRARY x_eval / x_base — it depends only on log_sigma.
#define T1_SKIP (-46.0f)

__device__ __forceinline__ float t1_of(float ls) {
    // t1 = -0.5 * D * log(2*pi) - log_sigma
    return -0.5f * (float)DDIM * 1.8378770664093453f - ls;
}

// Scratch (no allocations allowed — device globals)
__device__ float g_c[MDIM];
__device__ float g_d[NDIM];
__device__ float g_partial[NSPLIT * MDIM];

__device__ __forceinline__ float ex2_approx(float x) {
    float r;
    asm("ex2.approx.ftz.f32 %0, %1;" : "=f"(r) : "f"(x));
    return r;
}

// ---------------------------------------------------------------------------
// Kernel P: per-row constants in log2 domain (fallback path only).
// ---------------------------------------------------------------------------
__global__ void kde_precompute(const float* __restrict__ xe,
                               const float* __restrict__ xb,
                               const float* __restrict__ logsig) {
    float ls = logsig[0];
    float t1 = t1_of(ls);
    if (t1 <= T1_SKIP) return;   // provably-underflowed: nothing to do

    int i = blockIdx.x * blockDim.x + threadIdx.x;
    float inv_s2 = __expf(-2.0f * ls);

    if (i < MDIM) {
        const float4* p = (const float4*)(xe + (size_t)i * DDIM);
        float s = 0.0f;
#pragma unroll
        for (int k = 0; k < DDIM / 4; k++) {
            float4 v = p[k];
            s += v.x * v.x + v.y * v.y + v.z * v.z + v.w * v.w;
        }
        g_c[i] = (t1 - 0.5f * s * inv_s2) * LOG2E;
    }
    int j = i - MDIM;
    if (j >= 0 && j < NDIM) {
        const float4* p = (const float4*)(xb + (size_t)j * DDIM);
        float s = 0.0f;
#pragma unroll
        for (int k = 0; k < DDIM / 4; k++) {
            float4 v = p[k];
            s += v.x * v.x + v.y * v.y + v.z * v.z + v.w * v.w;
        }
        g_d[j] = (-0.5f * s * inv_s2) * LOG2E;
    }
}

// ---------------------------------------------------------------------------
// Main kernel (fallback path): 128x128 tile, 256 threads, 8x8 register tile.
// ---------------------------------------------------------------------------
__global__ __launch_bounds__(256)
void kde_main(const float* __restrict__ xe,
              const float* __restrict__ xb,
              const float* __restrict__ logsig) {
    const float ls = logsig[0];
    if (t1_of(ls) <= T1_SKIP) return;   // global underflow: result is log(EPS)

    extern __shared__ float sm[];
    float* As = sm;
    float* Bs = sm + DDIM * SSTRIDE;

    const int tid = threadIdx.x;
    const int ty = tid >> 4;
    const int tx = tid & 15;
    const int m0 = blockIdx.x * BM;
    const int c0 = blockIdx.y * NCOLS;

    const float gscale = __expf(-2.0f * ls) * LOG2E;

    {
        const float4* xe4 = (const float4*)xe;
#pragma unroll
        for (int it = 0; it < (BM * (DDIM / 4)) / 256; it++) {
            int i = it * 256 + tid;
            int row = i >> 4;
            int k4 = i & 15;
            float4 v = xe4[(size_t)(m0 + row) * (DDIM / 4) + k4];
            int k = k4 * 4;
            As[(k + 0) * SSTRIDE + row] = v.x;
            As[(k + 1) * SSTRIDE + row] = v.y;
            As[(k + 2) * SSTRIDE + row] = v.z;
            As[(k + 3) * SSTRIDE + row] = v.w;
        }
    }

    float cm[8];
#pragma unroll
    for (int u = 0; u < 4; u++) {
        cm[u]     = __ldg(&g_c[m0 + ty * 4 + u]);
        cm[u + 4] = __ldg(&g_c[m0 + 64 + ty * 4 + u]);
    }

    float rowacc[8];
#pragma unroll
    for (int u = 0; u < 8; u++) rowacc[u] = 0.0f;

    const float4* xb4 = (const float4*)xb;

    for (int t = 0; t < NTILES; t++) {
        const int n0 = c0 + t * BN;
        __syncthreads();
#pragma unroll
        for (int it = 0; it < (BN * (DDIM / 4)) / 256; it++) {
            int i = it * 256 + tid;
            int row = i >> 4;
            int k4 = i & 15;
            float4 v = xb4[(size_t)(n0 + row) * (DDIM / 4) + k4];
            int k = k4 * 4;
            Bs[(k + 0) * SSTRIDE + row] = v.x;
            Bs[(k + 1) * SSTRIDE + row] = v.y;
            Bs[(k + 2) * SSTRIDE + row] = v.z;
            Bs[(k + 3) * SSTRIDE + row] = v.w;
        }
        __syncthreads();

        float dn[8];
#pragma unroll
        for (int u = 0; u < 4; u++) {
            dn[u]     = __ldg(&g_d[n0 + tx * 4 + u]);
            dn[u + 4] = __ldg(&g_d[n0 + 64 + tx * 4 + u]);
        }

        float cross[8][8];
#pragma unroll
        for (int i = 0; i < 8; i++)
#pragma unroll
            for (int j = 0; j < 8; j++) cross[i][j] = 0.0f;

#pragma unroll 8
        for (int k = 0; k < DDIM; k++) {
            float4 a0 = *(const float4*)&As[k * SSTRIDE + ty * 4];
            float4 a1 = *(const float4*)&As[k * SSTRIDE + 64 + ty * 4];
            float4 b0 = *(const float4*)&Bs[k * SSTRIDE + tx * 4];
            float4 b1 = *(const float4*)&Bs[k * SSTRIDE + 64 + tx * 4];
            float a[8] = {a0.x, a0.y, a0.z, a0.w, a1.x, a1.y, a1.z, a1.w};
            float b[8] = {b0.x, b0.y, b0.z, b0.w, b1.x, b1.y, b1.z, b1.w};
#pragma unroll
            for (int i = 0; i < 8; i++)
#pragma unroll
                for (int j = 0; j < 8; j++)
                    cross[i][j] = fmaf(a[i], b[j], cross[i][j]);
        }

        float mxi[8];
#pragma unroll
        for (int i = 0; i < 8; i++) {
            float mi = -1e30f;
#pragma unroll
            for (int j = 0; j < 8; j++) {
                float e = fmaf(cross[i][j], gscale, cm[i] + dn[j]);
                cross[i][j] = e;
                mi = fmaxf(mi, e);
            }
            mxi[i] = mi;
        }
        float mx = fmaxf(fmaxf(fmaxf(mxi[0], mxi[1]), fmaxf(mxi[2], mxi[3])),
                         fmaxf(fmaxf(mxi[4], mxi[5]), fmaxf(mxi[6], mxi[7])));
        if (mx > -125.0f) {
#pragma unroll
            for (int i = 0; i < 8; i++) {
                float s = 0.0f;
#pragma unroll
                for (int j = 0; j < 8; j++) s += ex2_approx(cross[i][j]);
                rowacc[i] += s;
            }
        }
    }

#pragma unroll
    for (int u = 0; u < 8; u++) {
        float v = rowacc[u];
#pragma unroll
        for (int o = 1; o < 16; o <<= 1)
            v += __shfl_xor_sync(0xffffffffu, v, o);
        if (tx == 0) {
            int mrow = (u < 4) ? (m0 + ty * 4 + u) : (m0 + 64 + ty * 4 + (u - 4));
            g_partial[blockIdx.y * MDIM + mrow] = v;
        }
    }
}

// ---------------------------------------------------------------------------
// Finalize: either the provably-underflowed constant, or the full reduction.
// ---------------------------------------------------------------------------
__global__ void kde_finalize(const float* __restrict__ logsig,
                             float* __restrict__ out) {
    int m = blockIdx.x * blockDim.x + threadIdx.x;
    if (m >= MDIM) return;

    float ls = logsig[0];
    if (t1_of(ls) <= T1_SKIP) {
        // val <= exp(T1_SKIP) = 1e-20  =>  log(EPS + val) == log(EPS) in fp32
        out[m] = logf(EPSV);
        return;
    }

    float s = 0.0f;
#pragma unroll
    for (int g = 0; g < NSPLIT; g++) s += g_partial[g * MDIM + m];
    out[m] = logf(EPSV + s * (1.0f / (float)NDIM));
}

// ---------------------------------------------------------------------------
extern "C" void kernel_launch(void* const* d_in, const int* in_sizes, int n_in,
                              void* d_out, int out_size) {
    const float* xe = (const float*)d_in[0];   // x_eval [4096,64]
    const float* xb = (const float*)d_in[1];   // x_base [8192,64]
    const float* ls = (const float*)d_in[2];   // log_sigma [1]
    float* out = (float*)d_out;                // [4096]

    size_t smem = (size_t)2 * DDIM * SSTRIDE * sizeof(float);  // 67584 B
    cudaFuncSetAttribute(kde_main, cudaFuncAttributeMaxDynamicSharedMemorySize,
                         (int)smem);

    kde_precompute<<<(MDIM + NDIM + 255) / 256, 256>>>(xe, xb, ls);
    dim3 grid(MDIM / BM, NSPLIT);
    kde_main<<<grid, 256, smem>>>(xe, xb, ls);
    kde_finalize<<<(MDIM + 255) / 256, 256>>>(ls, out);
}

// round 4
// speedup vs baseline: 43.1259x; 1.4685x over previous
#include <cuda_runtime.h>
#include <math.h>

// Problem constants
#define MDIM 4096
#define NDIM 8192
#define DDIM 64

// Tiling (fallback GEMM path; one block owns 128 full rows)
#define BM 128
#define BN 128
#define NT (NDIM / BN)          // 64 column tiles per block
#define SSTRIDE 132             // smem k-major row stride in floats

#define LOG2E 1.4426950408889634f
#define EPSV  1e-8f

// Global-skip bound: t2 = -0.5*sq/sigma^2 <= 0 always (sq is a squared
// distance), so val = (1/n) * sum exp(t1 + t2) <= exp(t1).
// If t1 <= T1_SKIP (= -46): val <= 1e-20, and
//   |log(EPS + val) - log(EPS)| <= val/EPS <= 1e-12   (below fp32 ulp).
// Holds for ARBITRARY x_eval / x_base — depends only on log_sigma.
#define T1_SKIP (-46.0f)

__device__ __forceinline__ float t1_of(float ls) {
    // t1 = -0.5 * D * log(2*pi) - log_sigma
    return -0.5f * (float)DDIM * 1.8378770664093453f - ls;
}

__device__ __forceinline__ float ex2_approx(float x) {
    float r;
    asm("ex2.approx.ftz.f32 %0, %1;" : "=f"(r) : "f"(x));
    return r;
}

// ---------------------------------------------------------------------------
// Single fused kernel. Grid = 32 blocks, each owns rows [m0, m0+128).
//  - Skip path (provable underflow): write log(EPS) for our rows, exit.
//  - Fallback: full KDE for our 128 rows across all N columns, with
//    per-row/per-col constants computed in-block. No scratch, no 2nd kernel.
// ---------------------------------------------------------------------------
__global__ __launch_bounds__(256)
void kde_fused(const float* __restrict__ xe,
               const float* __restrict__ xb,
               const float* __restrict__ logsig,
               float* __restrict__ out) {
    const int tid = threadIdx.x;
    const int m0 = blockIdx.x * BM;

    const float ls = logsig[0];
    const float t1 = t1_of(ls);

    if (t1 <= T1_SKIP) {
        // Entire sum provably below fp32 visibility: out = log(EPS) everywhere.
        if (tid < BM) out[m0 + tid] = logf(EPSV);
        return;
    }

    // ---------------- fallback: exact fused KDE ----------------
    extern __shared__ float sm[];
    float* As = sm;                       // [DDIM][SSTRIDE] eval tile, k-major
    float* Bs = sm + DDIM * SSTRIDE;      // [DDIM][SSTRIDE] base tile, k-major
    __shared__ float sc[BM];              // row constants (log2 domain)
    __shared__ float sd[BN];              // col constants (log2 domain)

    const int ty = tid >> 4;              // 0..15
    const int tx = tid & 15;              // 0..15

    const float inv_s2 = __expf(-2.0f * ls);
    const float gscale = inv_s2 * LOG2E;  // multiplies cross term

    const float4* xe4 = (const float4*)xe;
    const float4* xb4 = (const float4*)xb;

    // Load + transpose eval tile; compute row constants.
#pragma unroll
    for (int it = 0; it < (BM * (DDIM / 4)) / 256; it++) {
        int i = it * 256 + tid;
        int row = i >> 4;
        int k4 = i & 15;
        float4 v = xe4[(size_t)(m0 + row) * (DDIM / 4) + k4];
        int k = k4 * 4;
        As[(k + 0) * SSTRIDE + row] = v.x;
        As[(k + 1) * SSTRIDE + row] = v.y;
        As[(k + 2) * SSTRIDE + row] = v.z;
        As[(k + 3) * SSTRIDE + row] = v.w;
    }
    if (tid < BM) {
        const float4* p = xe4 + (size_t)(m0 + tid) * (DDIM / 4);
        float s = 0.0f;
#pragma unroll
        for (int k = 0; k < DDIM / 4; k++) {
            float4 v = p[k];
            s += v.x * v.x + v.y * v.y + v.z * v.z + v.w * v.w;
        }
        sc[tid] = (t1 - 0.5f * s * inv_s2) * LOG2E;
    }
    __syncthreads();

    float cm[8];
#pragma unroll
    for (int u = 0; u < 4; u++) {
        cm[u]     = sc[ty * 4 + u];
        cm[u + 4] = sc[64 + ty * 4 + u];
    }

    float rowacc[8];
#pragma unroll
    for (int u = 0; u < 8; u++) rowacc[u] = 0.0f;

    for (int t = 0; t < NT; t++) {
        const int n0 = t * BN;
        __syncthreads();   // protect Bs/sd from previous iteration's readers
        // Load + transpose base tile; compute col constants.
#pragma unroll
        for (int it = 0; it < (BN * (DDIM / 4)) / 256; it++) {
            int i = it * 256 + tid;
            int row = i >> 4;
            int k4 = i & 15;
            float4 v = xb4[(size_t)(n0 + row) * (DDIM / 4) + k4];
            int k = k4 * 4;
            Bs[(k + 0) * SSTRIDE + row] = v.x;
            Bs[(k + 1) * SSTRIDE + row] = v.y;
            Bs[(k + 2) * SSTRIDE + row] = v.z;
            Bs[(k + 3) * SSTRIDE + row] = v.w;
        }
        if (tid < BN) {
            const float4* p = xb4 + (size_t)(n0 + tid) * (DDIM / 4);
            float s = 0.0f;
#pragma unroll
            for (int k = 0; k < DDIM / 4; k++) {
                float4 v = p[k];
                s += v.x * v.x + v.y * v.y + v.z * v.z + v.w * v.w;
            }
            sd[tid] = (-0.5f * s * inv_s2) * LOG2E;
        }
        __syncthreads();

        float dn[8];
#pragma unroll
        for (int u = 0; u < 4; u++) {
            dn[u]     = sd[tx * 4 + u];
            dn[u + 4] = sd[64 + tx * 4 + u];
        }

        float cross[8][8];
#pragma unroll
        for (int i = 0; i < 8; i++)
#pragma unroll
            for (int j = 0; j < 8; j++) cross[i][j] = 0.0f;

#pragma unroll 8
        for (int k = 0; k < DDIM; k++) {
            float4 a0 = *(const float4*)&As[k * SSTRIDE + ty * 4];
            float4 a1 = *(const float4*)&As[k * SSTRIDE + 64 + ty * 4];
            float4 b0 = *(const float4*)&Bs[k * SSTRIDE + tx * 4];
            float4 b1 = *(const float4*)&Bs[k * SSTRIDE + 64 + tx * 4];
            float a[8] = {a0.x, a0.y, a0.z, a0.w, a1.x, a1.y, a1.z, a1.w};
            float b[8] = {b0.x, b0.y, b0.z, b0.w, b1.x, b1.y, b1.z, b1.w};
#pragma unroll
            for (int i = 0; i < 8; i++)
#pragma unroll
                for (int j = 0; j < 8; j++)
                    cross[i][j] = fmaf(a[i], b[j], cross[i][j]);
        }

        // Epilogue: log2-domain exponent + per-thread-tile underflow skip.
        float mxi[8];
#pragma unroll
        for (int i = 0; i < 8; i++) {
            float mi = -1e30f;
#pragma unroll
            for (int j = 0; j < 8; j++) {
                float e = fmaf(cross[i][j], gscale, cm[i] + dn[j]);
                cross[i][j] = e;
                mi = fmaxf(mi, e);
            }
            mxi[i] = mi;
        }
        float mx = fmaxf(fmaxf(fmaxf(mxi[0], mxi[1]), fmaxf(mxi[2], mxi[3])),
                         fmaxf(fmaxf(mxi[4], mxi[5]), fmaxf(mxi[6], mxi[7])));
        if (mx > -125.0f) {   // below 2^-125 the fp32 sum is unchanged
#pragma unroll
            for (int i = 0; i < 8; i++) {
                float s = 0.0f;
#pragma unroll
                for (int j = 0; j < 8; j++) s += ex2_approx(cross[i][j]);
                rowacc[i] += s;
            }
        }
    }

    // Reduce across the 16 column threads; write final output directly.
#pragma unroll
    for (int u = 0; u < 8; u++) {
        float v = rowacc[u];
#pragma unroll
        for (int o = 1; o < 16; o <<= 1)
            v += __shfl_xor_sync(0xffffffffu, v, o);
        if (tx == 0) {
            int mrow = (u < 4) ? (m0 + ty * 4 + u) : (m0 + 64 + ty * 4 + (u - 4));
            out[mrow] = logf(EPSV + v * (1.0f / (float)NDIM));
        }
    }
}

// ---------------------------------------------------------------------------
extern "C" void kernel_launch(void* const* d_in, const int* in_sizes, int n_in,
                              void* d_out, int out_size) {
    const float* xe = (const float*)d_in[0];   // x_eval [4096,64]
    const float* xb = (const float*)d_in[1];   // x_base [8192,64]
    const float* ls = (const float*)d_in[2];   // log_sigma [1]
    float* out = (float*)d_out;                // [4096]

    size_t smem = (size_t)2 * DDIM * SSTRIDE * sizeof(float);  // 67584 B
    cudaFuncSetAttribute(kde_fused, cudaFuncAttributeMaxDynamicSharedMemorySize,
                         (int)smem);

    kde_fused<<<MDIM / BM, 256, smem>>>(xe, xb, ls, out);
}